// round 9
// baseline (speedup 1.0000x reference)
#include <cuda_runtime.h>
#include <cuda_bf16.h>
#include <cstdint>

#define Bn 8
#define CN 64
#define CL 32
#define CH 128
#define Himg 256
#define HMimg 512
#define SLOPE 0.2f
#define GAINF 1.4142135623730951f
#define EPSV 1e-5f

__device__ uint2 g_fB1[1024];   // [kt2][nt16][lane32] -> (pair0,pair1) bf16x2
__device__ uint2 g_fB2[4096];   // [kt8][nt16][lane32] -> (pair0,pair1) bf16x2
// layout: [b][chgroup(8)][px(65536)][4ch] bf16  (one uint2 per (px,group))
__device__ __nv_bfloat16 g_v[(size_t)Bn * 8 * 65536 * 4];
__device__ unsigned g_gb[(size_t)Bn * CN * 65536];      // packed (gamma,beta) bf16x2

static __device__ __forceinline__ unsigned pack_bf16x2(float a, float b) {
    __nv_bfloat162 t = __floats2bfloat162_rn(a, b);
    return *reinterpret_cast<unsigned*>(&t);
}

// ---- packed fp32x2 helpers (B300 FFMA2 path) ----
static __device__ __forceinline__ uint64_t pk2(float lo, float hi) {
    uint64_t r; asm("mov.b64 %0, {%1,%2};" : "=l"(r) : "f"(lo), "f"(hi)); return r;
}
static __device__ __forceinline__ void upk2(uint64_t v, float& lo, float& hi) {
    asm("mov.b64 {%0,%1}, %2;" : "=f"(lo), "=f"(hi) : "l"(v));
}
static __device__ __forceinline__ uint64_t ffma2(uint64_t a, uint64_t b, uint64_t c) {
    uint64_t d; asm("fma.rn.f32x2 %0, %1, %2, %3;" : "=l"(d) : "l"(a), "l"(b), "l"(c)); return d;
}

// ---------------- FIR downsample: 32x32 out-tile, 4 channels per block ----------------
// grid (8, 8, 64): x=col-tile(32), y=row-tile(32), z = b*8 + chgroup
// Also builds the GEMM weight-fragment tables (blocks z==0,y==0).
__global__ void __launch_bounds__(256, 2)
fir_kernel(const float* __restrict__ hm, const float* __restrict__ F,
           const float* __restrict__ w_shared,
           const float* __restrict__ w_gamma,
           const float* __restrict__ w_beta) {
    __shared__ float sint[4 * 74 * 32];   // 37888 B

    const int tid = threadIdx.x;
    const int x0 = blockIdx.x * 32;
    const int y0 = blockIdx.y * 32;

    // ---- weight-fragment table build (8 blocks do 1/8 each; gemm runs later) ----
    if (blockIdx.z == 0 && blockIdx.y == 0) {
        int slice = blockIdx.x;
        if (tid < 128) {
            int e = slice * 128 + tid;          // uint2 entry of g_fB1
            unsigned v[2];
#pragma unroll
            for (int h = 0; h < 2; h++) {
                int u = 2 * e + h;
                int pair = u & 1;
                int lane = (u >> 1) & 31;
                int nt = (u >> 6) & 15;
                int kt = u >> 10;
                int gid = lane >> 2, tig = lane & 3;
                int n = nt * 8 + gid;
                int k = kt * 16 + tig * 2 + pair * 8;
                v[h] = pack_bf16x2(__ldg(&w_shared[n * CL + k]),
                                   __ldg(&w_shared[n * CL + k + 1]));
            }
            g_fB1[e] = make_uint2(v[0], v[1]);
        }
        for (int e = slice * 512 + tid; e < (slice + 1) * 512; e += 256) {
            unsigned v[2];
#pragma unroll
            for (int h = 0; h < 2; h++) {
                int u = 2 * e + h;
                int pair = u & 1;
                int lane = (u >> 1) & 31;
                int nt = (u >> 6) & 15;
                int kt = u >> 10;
                int gid = lane >> 2, tig = lane & 3;
                int n = nt * 8 + gid;
                int k = kt * 16 + tig * 2 + pair * 8;
                float a0, a1;
                if (n < 64) { a0 = __ldg(&w_gamma[n * CH + k]); a1 = __ldg(&w_gamma[n * CH + k + 1]); }
                else        { a0 = __ldg(&w_beta[(n - 64) * CH + k]); a1 = __ldg(&w_beta[(n - 64) * CH + k + 1]); }
                v[h] = pack_bf16x2(a0, a1);
            }
            g_fB2[e] = make_uint2(v[0], v[1]);
        }
    }

    // flipped 1D filter from rank-1 F, packed broadcast pairs
    uint64_t aa[12];
    {
        float rs = rsqrtf(__ldg(&F[5 * 12 + 5]));
#pragma unroll
        for (int j = 0; j < 12; j++) {
            float a = __ldg(&F[(11 - j) * 12 + 5]) * rs;
            aa[j] = pk2(a, a);
        }
    }

    const float* hmb = hm + ((size_t)((blockIdx.z >> 3) * CL + (blockIdx.z & 7) * 4)) * (HMimg * HMimg);
    const bool interior = (blockIdx.x >= 1) & (blockIdx.x <= 6) &
                          (blockIdx.y >= 1) & (blockIdx.y <= 6);

    // ---- phase 1: horizontal FIR (stride 2), channel-PAIRS via f32x2 ----
    // tasks: 2 chpairs x 74 rows x 8 quads = 1184
    for (int t = tid; t < 1184; t += 256) {
        int cp = t / 592;
        int rem = t - cp * 592;
        int r = rem >> 3;
        int oq = rem & 7;
        int gr = 2 * y0 - 5 + r;
        int cb = 2 * x0 - 8 + oq * 8;     // 16B-aligned base col (taps use cb+3..cb+20)
        int c0 = cp * 2;
        const float* p0 = hmb + (size_t)c0 * (HMimg * HMimg) + (size_t)gr * HMimg;
        const float* p1 = p0 + (HMimg * HMimg);

        uint64_t w2[18];                  // (ch0, ch1) pairs for taps 3..20
        if (interior) {
#pragma unroll
            for (int q6 = 0; q6 < 6; q6++) {
                float4 v0 = __ldg(reinterpret_cast<const float4*>(p0 + cb) + q6);
                float4 v1 = __ldg(reinterpret_cast<const float4*>(p1 + cb) + q6);
                float a0[4] = {v0.x, v0.y, v0.z, v0.w};
                float a1[4] = {v1.x, v1.y, v1.z, v1.w};
#pragma unroll
                for (int k = 0; k < 4; k++) {
                    int idx = q6 * 4 + k;
                    if (idx >= 3 && idx < 21) w2[idx - 3] = pk2(a0[k], a1[k]);
                }
            }
        } else {
            bool rok = ((unsigned)gr < 512u);
#pragma unroll
            for (int i = 0; i < 18; i++) {
                int col = cb + 3 + i;
                bool ok = rok && ((unsigned)col < 512u);
                float l0 = ok ? __ldg(p0 + col) : 0.f;
                float l1 = ok ? __ldg(p1 + col) : 0.f;
                w2[i] = pk2(l0, l1);
            }
        }
        float lo[4], hi[4];
#pragma unroll
        for (int q = 0; q < 4; q++) {
            uint64_t acc = 0ull;
#pragma unroll
            for (int j = 0; j < 12; j++) acc = ffma2(w2[2 * q + j], aa[j], acc);
            upk2(acc, lo[q], hi[q]);
        }
        *reinterpret_cast<float4*>(&sint[(c0 * 74 + r) * 32 + oq * 4]) =
            make_float4(lo[0], lo[1], lo[2], lo[3]);
        *reinterpret_cast<float4*>(&sint[((c0 + 1) * 74 + r) * 32 + oq * 4]) =
            make_float4(hi[0], hi[1], hi[2], hi[3]);
    }
    __syncthreads();

    // ---- phase 2: vertical FIR (stride 2) over column-pairs via f32x2, fused pack+store ----
    // 256 tasks: og 0..15 (2 out rows each), oxp 0..15 (2 out cols each)
    {
        int og = tid >> 4;
        int oxp = tid & 15;
        int ox = oxp * 2;
        float rlo[2][4], rhi[2][4];
#pragma unroll
        for (int c = 0; c < 4; c++) {
            const float* ip = &sint[(c * 74 + 4 * og) * 32 + ox];
            uint64_t wl[14];
#pragma unroll
            for (int k = 0; k < 14; k++)
                wl[k] = *reinterpret_cast<const uint64_t*>(ip + k * 32);
            uint64_t a0 = 0ull, a1 = 0ull;
#pragma unroll
            for (int j = 0; j < 12; j++) {
                a0 = ffma2(wl[j], aa[j], a0);
                a1 = ffma2(wl[j + 2], aa[j], a1);
            }
            upk2(a0, rlo[0][c], rhi[0][c]);
            upk2(a1, rlo[1][c], rhi[1][c]);
        }
        uint2* vbase = reinterpret_cast<uint2*>(g_v) + ((size_t)blockIdx.z << 16);
#pragma unroll
        for (int rr = 0; rr < 2; rr++) {
            int gy = y0 + 2 * og + rr;
            uint4 st;
            st.x = pack_bf16x2(rlo[rr][0], rlo[rr][1]);
            st.y = pack_bf16x2(rlo[rr][2], rlo[rr][3]);
            st.z = pack_bf16x2(rhi[rr][0], rhi[rr][1]);
            st.w = pack_bf16x2(rhi[rr][2], rhi[rr][3]);
            *reinterpret_cast<uint4*>(&vbase[(size_t)gy * Himg + x0 + ox]) = st;
        }
    }
}

// ---------------- mma helpers ----------------
static __device__ __forceinline__ void ldsm4(unsigned r[4], unsigned addr) {
    asm volatile("ldmatrix.sync.aligned.m8n8.x4.shared.b16 {%0,%1,%2,%3}, [%4];"
                 : "=r"(r[0]), "=r"(r[1]), "=r"(r[2]), "=r"(r[3])
                 : "r"(addr) : "memory");
}
static __device__ __forceinline__ void mma_bf16(float c[4], const unsigned a[4],
                                                unsigned b0, unsigned b1) {
    asm("mma.sync.aligned.m16n8k16.row.col.f32.bf16.bf16.f32 "
        "{%0,%1,%2,%3}, {%4,%5,%6,%7}, {%8,%9}, {%0,%1,%2,%3};"
        : "+f"(c[0]), "+f"(c[1]), "+f"(c[2]), "+f"(c[3])
        : "r"(a[0]), "r"(a[1]), "r"(a[2]), "r"(a[3]), "r"(b0), "r"(b1));
}

// ---------------- GEMM1 + GEMM2 -> packed gamma/beta ----------------
// grid (512, 8): 128 consecutive px per block. 8 warps as 4(M) x 2(N).
__global__ void __launch_bounds__(256, 2)
gemm_kernel(const float* __restrict__ b_shared,
            const float* __restrict__ b_gamma,
            const float* __restrict__ b_beta) {
    __shared__ __nv_bfloat16 sh[128 * 136];      // also aliased as sv[128][40] during A-stage
    __nv_bfloat16* sv = sh;

    const int tid = threadIdx.x;
    const int lane = tid & 31;
    const int warp = tid >> 5;
    const int b = blockIdx.y;
    const int px0 = blockIdx.x * 128;

    // stage A: v from [b][g][px][4] layout -> sv[128][40]
    {
        const uint2* src = reinterpret_cast<const uint2*>(g_v) + (((size_t)b * 8) << 16) + px0;
        for (int e = tid; e < 1024; e += 256) {
            int g = e >> 7, px = e & 127;
            uint2 v = __ldg(&src[((size_t)g << 16) + px]);
            *reinterpret_cast<uint2*>(&sv[px * 40 + g * 4]) = v;
        }
    }
    __syncthreads();

    const int mrow = warp & 3;            // 0..3 -> M offset 32*mrow
    const int ncol = warp >> 2;           // 0..1 -> N offset 64*ncol
    const int mbase = mrow * 32;
    const int gid = lane >> 2, tig = lane & 3;
    const int r16 = lane & 15;
    const int khalf = (lane >> 4) << 3;

    unsigned sbase = (unsigned)__cvta_generic_to_shared(sh);

    // ---- GEMM1: load A fragments up-front (sv will be overwritten by sh) ----
    unsigned A1[2][2][4];
#pragma unroll
    for (int mt = 0; mt < 2; mt++)
#pragma unroll
        for (int kt = 0; kt < 2; kt++)
            ldsm4(A1[mt][kt], sbase + ((mbase + mt * 16 + r16) * 40 + khalf + kt * 16) * 2);
    __syncthreads();

    {
        float acc[2][8][4];
#pragma unroll
        for (int mt = 0; mt < 2; mt++)
#pragma unroll
            for (int nt = 0; nt < 8; nt++)
#pragma unroll
                for (int i = 0; i < 4; i++) acc[mt][nt][i] = 0.f;
#pragma unroll
        for (int kt = 0; kt < 2; kt++)
#pragma unroll
            for (int nt = 0; nt < 8; nt++) {
                uint2 bb = __ldg(&g_fB1[(kt * 16 + ncol * 8 + nt) * 32 + lane]);
                mma_bf16(acc[0][nt], A1[0][kt], bb.x, bb.y);
                mma_bf16(acc[1][nt], A1[1][kt], bb.x, bb.y);
            }
        // epilogue1: bias + lrelu*gain -> sh (bf16)
#pragma unroll
        for (int mt = 0; mt < 2; mt++) {
            const int r0 = mbase + mt * 16 + gid;
#pragma unroll
            for (int nt = 0; nt < 8; nt++) {
                int c0 = (ncol * 8 + nt) * 8 + tig * 2;
                float bb0 = __ldg(&b_shared[c0]), bb1 = __ldg(&b_shared[c0 + 1]);
                float v00 = acc[mt][nt][0] + bb0, v01 = acc[mt][nt][1] + bb1;
                float v10 = acc[mt][nt][2] + bb0, v11 = acc[mt][nt][3] + bb1;
                v00 = (v00 >= 0.f ? v00 : v00 * SLOPE) * GAINF;
                v01 = (v01 >= 0.f ? v01 : v01 * SLOPE) * GAINF;
                v10 = (v10 >= 0.f ? v10 : v10 * SLOPE) * GAINF;
                v11 = (v11 >= 0.f ? v11 : v11 * SLOPE) * GAINF;
                *reinterpret_cast<__nv_bfloat162*>(&sh[r0 * 136 + c0]) =
                    __floats2bfloat162_rn(v00, v01);
                *reinterpret_cast<__nv_bfloat162*>(&sh[(r0 + 8) * 136 + c0]) =
                    __floats2bfloat162_rn(v10, v11);
            }
        }
    }
    __syncthreads();

    // ---- GEMM2: gb = h * W2^T ----
    float acc2[2][8][4];
#pragma unroll
    for (int mt = 0; mt < 2; mt++)
#pragma unroll
        for (int nt = 0; nt < 8; nt++)
#pragma unroll
            for (int i = 0; i < 4; i++) acc2[mt][nt][i] = 0.f;
#pragma unroll
    for (int kt = 0; kt < 8; kt++) {
        unsigned A[2][4];
        ldsm4(A[0], sbase + ((mbase + r16) * 136 + khalf + kt * 16) * 2);
        ldsm4(A[1], sbase + ((mbase + 16 + r16) * 136 + khalf + kt * 16) * 2);
#pragma unroll
        for (int nt = 0; nt < 8; nt++) {
            uint2 bb = __ldg(&g_fB2[(kt * 16 + ncol * 8 + nt) * 32 + lane]);
            mma_bf16(acc2[0][nt], A[0], bb.x, bb.y);
            mma_bf16(acc2[1][nt], A[1], bb.x, bb.y);
        }
    }
    __syncthreads();  // all ldsm reads of sh complete before overwrite

    // epilogue2: + bias -> sh (bf16)
#pragma unroll
    for (int mt = 0; mt < 2; mt++) {
        const int r0 = mbase + mt * 16 + gid;
#pragma unroll
        for (int nt = 0; nt < 8; nt++) {
            int n0 = (ncol * 8 + nt) * 8 + tig * 2;
            float bb0 = (n0 < 64) ? __ldg(&b_gamma[n0]) : __ldg(&b_beta[n0 - 64]);
            float bb1 = (n0 + 1 < 64) ? __ldg(&b_gamma[n0 + 1]) : __ldg(&b_beta[n0 + 1 - 64]);
            *reinterpret_cast<__nv_bfloat162*>(&sh[r0 * 136 + n0]) =
                __floats2bfloat162_rn(acc2[mt][nt][0] + bb0, acc2[mt][nt][1] + bb1);
            *reinterpret_cast<__nv_bfloat162*>(&sh[(r0 + 8) * 136 + n0]) =
                __floats2bfloat162_rn(acc2[mt][nt][2] + bb0, acc2[mt][nt][3] + bb1);
        }
    }
    __syncthreads();

    // store packed (gamma,beta), STG.64 over pixel pairs, coalesced per channel plane
    {
        unsigned* gbp = g_gb + (((size_t)b * CN) << 16) + px0;
#pragma unroll 4
        for (int e = tid; e < 4096; e += 256) {
            int c = e >> 6;
            int px = (e & 63) * 2;
            uint2 st;
            st.x = pack_bf16x2(__bfloat162float(sh[px * 136 + c]),
                               __bfloat162float(sh[px * 136 + 64 + c]));
            st.y = pack_bf16x2(__bfloat162float(sh[(px + 1) * 136 + c]),
                               __bfloat162float(sh[(px + 1) * 136 + 64 + c]));
            *reinterpret_cast<uint2*>(&gbp[((size_t)c << 16) + px]) = st;
        }
    }
}

// ---------------- fused instance-norm stats + apply (one block per (b,c) plane) ----------------
__global__ void __launch_bounds__(512, 2)
norm_apply_kernel(const float* __restrict__ x, float* __restrict__ out) {
    const int bc = blockIdx.x;
    const int tid = threadIdx.x;
    const float4* xp = reinterpret_cast<const float4*>(x + (size_t)bc * 65536);
    float4* op = reinterpret_cast<float4*>(out + (size_t)bc * 65536);
    const uint4* gbp = reinterpret_cast<const uint4*>(g_gb + ((size_t)bc << 16));

    float s = 0.f, q = 0.f;
#pragma unroll 8
    for (int i = tid; i < 16384; i += 512) {
        float4 v = xp[i];
        s += (v.x + v.y) + (v.z + v.w);
        q += v.x * v.x + v.y * v.y + v.z * v.z + v.w * v.w;
    }
#pragma unroll
    for (int o = 16; o > 0; o >>= 1) {
        s += __shfl_down_sync(0xffffffffu, s, o);
        q += __shfl_down_sync(0xffffffffu, q, o);
    }
    __shared__ float ws[16], wq[16], stat[2];
    int w = tid >> 5;
    if ((tid & 31) == 0) { ws[w] = s; wq[w] = q; }
    __syncthreads();
    if (tid == 0) {
        float S = 0.f, Q = 0.f;
#pragma unroll
        for (int i = 0; i < 16; i++) { S += ws[i]; Q += wq[i]; }
        float mu = S * (1.f / 65536.f);
        float var = Q * (1.f / 65536.f) - mu * mu;
        stat[0] = mu;
        stat[1] = rsqrtf(var + EPSV);
    }
    __syncthreads();
    const float mu = stat[0];
    const float rstd = stat[1];

#pragma unroll 4
    for (int i = tid; i < 16384; i += 512) {
        float4 v = xp[i];
        uint4 g = gbp[i];
        float4 r;
        {
            __nv_bfloat162 p = *reinterpret_cast<__nv_bfloat162*>(&g.x);
            float xn = (v.x - mu) * rstd;
            r.x = xn * (1.f + __bfloat162float(p.x)) + __bfloat162float(p.y) + 0.1f * v.x;
        }
        {
            __nv_bfloat162 p = *reinterpret_cast<__nv_bfloat162*>(&g.y);
            float xn = (v.y - mu) * rstd;
            r.y = xn * (1.f + __bfloat162float(p.x)) + __bfloat162float(p.y) + 0.1f * v.y;
        }
        {
            __nv_bfloat162 p = *reinterpret_cast<__nv_bfloat162*>(&g.z);
            float xn = (v.z - mu) * rstd;
            r.z = xn * (1.f + __bfloat162float(p.x)) + __bfloat162float(p.y) + 0.1f * v.z;
        }
        {
            __nv_bfloat162 p = *reinterpret_cast<__nv_bfloat162*>(&g.w);
            float xn = (v.w - mu) * rstd;
            r.w = xn * (1.f + __bfloat162float(p.x)) + __bfloat162float(p.y) + 0.1f * v.w;
        }
        op[i] = r;
    }
}

extern "C" void kernel_launch(void* const* d_in, const int* in_sizes, int n_in,
                              void* d_out, int out_size) {
    (void)in_sizes; (void)n_in; (void)out_size;
    const float* x        = (const float*)d_in[0];
    const float* hm       = (const float*)d_in[1];
    const float* F        = (const float*)d_in[2];
    const float* w_shared = (const float*)d_in[3];
    const float* b_shared = (const float*)d_in[4];
    const float* w_gamma  = (const float*)d_in[5];
    const float* b_gamma  = (const float*)d_in[6];
    const float* w_beta   = (const float*)d_in[7];
    const float* b_beta   = (const float*)d_in[8];
    float* out = (float*)d_out;

    dim3 fgrid(8, 8, 64);
    fir_kernel<<<fgrid, 256>>>(hm, F, w_shared, w_gamma, w_beta);
    dim3 ggrid(512, 8);
    gemm_kernel<<<ggrid, 256>>>(b_shared, b_gamma, b_beta);
    norm_apply_kernel<<<Bn * CN, 512>>>(x, out);
}